// round 13
// baseline (speedup 1.0000x reference)
#include <cuda_runtime.h>
#include <cuda_bf16.h>
#include <mma.h>

using namespace nvcuda;

// Problem constants (fixed by setup_inputs)
#define H 512
#define T_TREES 1024

// ---------------- device scratch (no allocs allowed) ----------------
// bf16 hi/lo split operands
__device__ __nv_bfloat16 g_WsT_h[H * H], g_WsT_l[H * H];     // Wsum^T
__device__ __nv_bfloat16 g_WzfT_h[H * H], g_WzfT_l[H * H];   // Wzf^T
__device__ __nv_bfloat16 g_N_h[H * H],  g_N_l[H * H];        // N = M^T
__device__ __nv_bfloat16 g_N2_h[H * H], g_N2_l[H * H];       // N^2
__device__ __nv_bfloat16 g_G_h[H * H],  g_G_l[H * H];        // N^3
__device__ __nv_bfloat16 g_S_h[T_TREES * H], g_S_l[T_TREES * H]; // pooled sums
// fp32 copies needed by k_d
__device__ float g_Nf[H * H];
__device__ float g_N2f[H * H];
__device__ float g_c[H];
__device__ float g_d[H];

__device__ __forceinline__ void split2(float a, __nv_bfloat16* h, __nv_bfloat16* l) {
    __nv_bfloat16 hh = __float2bfloat16(a);
    *h = hh;
    *l = __float2bfloat16(a - __bfloat162float(hh));
}

// ---------------- pooling: S[t] = sum of 64 x-rows, split to bf16 hi/lo ----------------
__global__ __launch_bounds__(256) void k_pool(const float4* __restrict__ x4) {
    int tid = threadIdx.x;
    int t = blockIdx.x * 2 + (tid >> 7);   // 512 blocks -> 1024 trees
    int q = tid & 127;                     // float4 column (H/4 = 128)
    const float4* p = x4 + (size_t)t * 64 * 128 + q;
    float4 s = make_float4(0.f, 0.f, 0.f, 0.f);
#pragma unroll 16
    for (int r = 0; r < 64; ++r) {
        float4 v = p[(size_t)r * 128];
        s.x += v.x; s.y += v.y; s.z += v.z; s.w += v.w;
    }
    int base = t * H + q * 4;
    split2(s.x, &g_S_h[base + 0], &g_S_l[base + 0]);
    split2(s.y, &g_S_h[base + 1], &g_S_l[base + 1]);
    split2(s.z, &g_S_h[base + 2], &g_S_l[base + 2]);
    split2(s.w, &g_S_h[base + 3], &g_S_l[base + 3]);
}

// ---------------- prep: Wsum^T, Wzf^T (transpose + split) and c ----------------
// blocks 0..255: Wsum^T; 256..511: Wzf^T; 512..513: c = 4*(Wzf@bsum + bzf)
__global__ __launch_bounds__(256) void k_prep(const float* __restrict__ Wz,
                                              const float* __restrict__ Wzf,
                                              const float* __restrict__ bz,
                                              const float* __restrict__ bzf) {
    __shared__ float sh[1056];   // tile[32][33] = 1056 floats; c-path uses 512
    int b = blockIdx.x;
    int tid = threadIdx.x;
    int tx = tid & 31, ty = tid >> 5;  // 32 x 8
    float (*tile)[33] = reinterpret_cast<float (*)[33]>(sh);
    if (b < 256) {
        int bx = b & 15, by = b >> 4;
#pragma unroll
        for (int i = 0; i < 4; ++i) {
            int r = by * 32 + ty + i * 8;
            int c = bx * 32 + tx;
            float v = Wz[0 * H * H + r * H + c] + Wz[1 * H * H + r * H + c]
                    + Wz[2 * H * H + r * H + c] + Wz[3 * H * H + r * H + c];
            tile[ty + i * 8][tx] = v;
        }
        __syncthreads();
#pragma unroll
        for (int i = 0; i < 4; ++i) {
            int idx = (bx * 32 + ty + i * 8) * H + by * 32 + tx;
            split2(tile[tx][ty + i * 8], &g_WsT_h[idx], &g_WsT_l[idx]);
        }
    } else if (b < 512) {
        int bb = b - 256;
        int bx = bb & 15, by = bb >> 4;
#pragma unroll
        for (int i = 0; i < 4; ++i)
            tile[ty + i * 8][tx] = Wzf[(by * 32 + ty + i * 8) * H + bx * 32 + tx];
        __syncthreads();
#pragma unroll
        for (int i = 0; i < 4; ++i) {
            int idx = (bx * 32 + ty + i * 8) * H + by * 32 + tx;
            split2(tile[tx][ty + i * 8], &g_WzfT_h[idx], &g_WzfT_l[idx]);
        }
    } else {
        // c = 4 * (Wzf @ bsum + bzf); reads only raw inputs
        float* sb = sh;
#pragma unroll
        for (int i = 0; i < 2; ++i) {
            int hh = tid + i * 256;
            sb[hh] = bz[hh] + bz[H + hh] + bz[2 * H + hh] + bz[3 * H + hh];
        }
        __syncthreads();
        int j = (b - 512) * 256 + tid;
        float acc = 0.f;
#pragma unroll 8
        for (int h = 0; h < H; ++h)
            acc += Wzf[(size_t)j * H + h] * sb[h];
        g_c[j] = 4.0f * (acc + bzf[j]);
    }
}

// ---------------- d = 16 M^2 c + 4 M c + c  (via N = M^T) ----------------
__global__ __launch_bounds__(256) void k_d() {
    int j = blockIdx.x * 256 + threadIdx.x;
    float acc = 0.f;
#pragma unroll 8
    for (int h = 0; h < H; ++h) {
        float ch = g_c[h];
        acc += ch * (16.0f * g_N2f[h * H + j] + 4.0f * g_Nf[h * H + j]);
    }
    g_d[j] = acc + g_c[j];
}

// ---------------- bf16x2-split tensor-core GEMM ----------------
// C = A @ B where A = Ah+Al, B = Bh+Bl (bf16 hi/lo, row-major, ld = 512).
// 3 mma passes: hi*hi + hi*lo + lo*hi, fp32 accumulators.
// Block: 128 threads (4 warps, 2x2 warp grid, 32x32 per warp via 2x2 wmma frags).
// Tile 64x64, full K=512 in-block (no split-K, no combine).
// Epilogue: optional fp32 store, optional bf16 hi/lo re-split store, optional bias.
__global__ __launch_bounds__(128) void k_bgemm(
    const __nv_bfloat16* __restrict__ Ah, const __nv_bfloat16* __restrict__ Al,
    const __nv_bfloat16* __restrict__ Bh, const __nv_bfloat16* __restrict__ Bl,
    float* __restrict__ Cf,
    __nv_bfloat16* __restrict__ Ch, __nv_bfloat16* __restrict__ Cl,
    const float* __restrict__ bias)
{
    __shared__ __nv_bfloat16 sA[2][64][40];   // [hi/lo][row][k], pad 40 (80B rows)
    __shared__ __nv_bfloat16 sB[2][32][72];   // [hi/lo][k][col], pad 72 (144B rows)
    __shared__ float sC[64][68];              // epilogue staging (272B rows)

    const int tid = threadIdx.x;
    const int wid = tid >> 5;
    const int rb = blockIdx.x * 64, cb = blockIdx.y * 64;
    const int wr = (wid >> 1) * 32, wc = (wid & 1) * 32;

    wmma::fragment<wmma::accumulator, 16, 16, 16, float> acc[2][2];
#pragma unroll
    for (int i = 0; i < 2; ++i)
#pragma unroll
        for (int j = 0; j < 2; ++j)
            wmma::fill_fragment(acc[i][j], 0.0f);

    for (int k0 = 0; k0 < H; k0 += 32) {
        // load A tiles (64x32) hi+lo: 256 uint4 each, 2 per thread
#pragma unroll
        for (int rep = 0; rep < 2; ++rep) {
            int e = rep * 128 + tid;           // 0..255
            int row = e >> 2, kq = (e & 3) * 8;
            size_t go = (size_t)(rb + row) * H + k0 + kq;
            *reinterpret_cast<uint4*>(&sA[0][row][kq]) =
                *reinterpret_cast<const uint4*>(Ah + go);
            *reinterpret_cast<uint4*>(&sA[1][row][kq]) =
                *reinterpret_cast<const uint4*>(Al + go);
        }
        // load B tiles (32x64) hi+lo
#pragma unroll
        for (int rep = 0; rep < 2; ++rep) {
            int e = rep * 128 + tid;           // 0..255
            int kr = e >> 3, cq = (e & 7) * 8;
            size_t go = (size_t)(k0 + kr) * H + cb + cq;
            *reinterpret_cast<uint4*>(&sB[0][kr][cq]) =
                *reinterpret_cast<const uint4*>(Bh + go);
            *reinterpret_cast<uint4*>(&sB[1][kr][cq]) =
                *reinterpret_cast<const uint4*>(Bl + go);
        }
        __syncthreads();

#pragma unroll
        for (int kk = 0; kk < 32; kk += 16) {
            wmma::fragment<wmma::matrix_a, 16, 16, 16, __nv_bfloat16, wmma::row_major> ah[2], al[2];
            wmma::fragment<wmma::matrix_b, 16, 16, 16, __nv_bfloat16, wmma::row_major> bh[2], bl[2];
#pragma unroll
            for (int i = 0; i < 2; ++i) {
                wmma::load_matrix_sync(ah[i], &sA[0][wr + i * 16][kk], 40);
                wmma::load_matrix_sync(al[i], &sA[1][wr + i * 16][kk], 40);
            }
#pragma unroll
            for (int j = 0; j < 2; ++j) {
                wmma::load_matrix_sync(bh[j], &sB[0][kk][wc + j * 16], 72);
                wmma::load_matrix_sync(bl[j], &sB[1][kk][wc + j * 16], 72);
            }
#pragma unroll
            for (int i = 0; i < 2; ++i)
#pragma unroll
                for (int j = 0; j < 2; ++j) {
                    wmma::mma_sync(acc[i][j], ah[i], bh[j], acc[i][j]);
                    wmma::mma_sync(acc[i][j], ah[i], bl[j], acc[i][j]);
                    wmma::mma_sync(acc[i][j], al[i], bh[j], acc[i][j]);
                }
        }
        __syncthreads();
    }

    // stage accumulators to smem
#pragma unroll
    for (int i = 0; i < 2; ++i)
#pragma unroll
        for (int j = 0; j < 2; ++j)
            wmma::store_matrix_sync(&sC[wr + i * 16][wc + j * 16], acc[i][j], 68,
                                    wmma::mem_row_major);
    __syncthreads();

    // cooperative epilogue: 64x64 floats = 1024 float4, 8 per thread
#pragma unroll
    for (int rep = 0; rep < 8; ++rep) {
        int e = rep * 128 + tid;
        int row = e >> 4, cq = (e & 15) * 4;
        float4 v = *reinterpret_cast<float4*>(&sC[row][cq]);
        if (bias != nullptr) {
            v.x += bias[cb + cq + 0];
            v.y += bias[cb + cq + 1];
            v.z += bias[cb + cq + 2];
            v.w += bias[cb + cq + 3];
        }
        size_t o = (size_t)(rb + row) * H + cb + cq;
        if (Cf != nullptr)
            *reinterpret_cast<float4*>(&Cf[o]) = v;
        if (Ch != nullptr) {
            split2(v.x, &Ch[o + 0], &Cl[o + 0]);
            split2(v.y, &Ch[o + 1], &Cl[o + 1]);
            split2(v.z, &Ch[o + 2], &Cl[o + 2]);
            split2(v.w, &Ch[o + 3], &Cl[o + 3]);
        }
    }
}

// ---------------- launch: 7 kernels; pool on a side stream ----------------
extern "C" void kernel_launch(void* const* d_in, const int* in_sizes, int n_in,
                              void* d_out, int out_size) {
    const float* x   = (const float*)d_in[0];
    const float* Wz  = (const float*)d_in[1];
    const float* bz  = (const float*)d_in[2];
    const float* Wzf = (const float*)d_in[3];
    const float* bzf = (const float*)d_in[4];
    float* out = (float*)d_out;

    __nv_bfloat16 *pWsTh, *pWsTl, *pWzfTh, *pWzfTl, *pNh, *pNl, *pN2h, *pN2l,
                  *pGh, *pGl, *pSh, *pSl;
    float *pNf, *pN2f, *pD;
    cudaGetSymbolAddress((void**)&pWsTh,  g_WsT_h);
    cudaGetSymbolAddress((void**)&pWsTl,  g_WsT_l);
    cudaGetSymbolAddress((void**)&pWzfTh, g_WzfT_h);
    cudaGetSymbolAddress((void**)&pWzfTl, g_WzfT_l);
    cudaGetSymbolAddress((void**)&pNh,    g_N_h);
    cudaGetSymbolAddress((void**)&pNl,    g_N_l);
    cudaGetSymbolAddress((void**)&pN2h,   g_N2_h);
    cudaGetSymbolAddress((void**)&pN2l,   g_N2_l);
    cudaGetSymbolAddress((void**)&pGh,    g_G_h);
    cudaGetSymbolAddress((void**)&pGl,    g_G_l);
    cudaGetSymbolAddress((void**)&pSh,    g_S_h);
    cudaGetSymbolAddress((void**)&pSl,    g_S_l);
    cudaGetSymbolAddress((void**)&pNf,    g_Nf);
    cudaGetSymbolAddress((void**)&pN2f,   g_N2f);
    cudaGetSymbolAddress((void**)&pD,     g_d);

    // Lazy one-time stream/event creation (host-side only; no device memory).
    static cudaStream_t sB = nullptr;
    static cudaEvent_t evFork = nullptr, evPool = nullptr;
    if (sB == nullptr) {
        cudaStreamCreateWithFlags(&sB, cudaStreamNonBlocking);
        cudaEventCreateWithFlags(&evFork, cudaEventDisableTiming);
        cudaEventCreateWithFlags(&evPool, cudaEventDisableTiming);
    }

    // ---- fork: pool (pure DRAM) beside the compute-only weight chain ----
    cudaEventRecord(evFork, 0);
    cudaStreamWaitEvent(sB, evFork, 0);
    k_pool<<<512, 256, 0, sB>>>((const float4*)x);
    cudaEventRecord(evPool, sB);

    // ---- stream 0: weight chain (tensor-core GEMMs, no split-K) ----
    k_prep<<<514, 256>>>(Wz, Wzf, bz, bzf);    // WsT/WzfT hi-lo, c

    // N = WsT @ WzfT  (fp32 for k_d + hi/lo for next gemms)
    k_bgemm<<<dim3(8, 8), 128>>>(pWsTh, pWsTl, pWzfTh, pWzfTl,
                                 pNf, pNh, pNl, nullptr);
    // N2 = N @ N
    k_bgemm<<<dim3(8, 8), 128>>>(pNh, pNl, pNh, pNl,
                                 pN2f, pN2h, pN2l, nullptr);
    // G = N2 @ N  (hi/lo only)
    k_bgemm<<<dim3(8, 8), 128>>>(pN2h, pN2l, pNh, pNl,
                                 nullptr, pGh, pGl, nullptr);
    // d = 16 M^2 c + 4 M c + c
    k_d<<<2, 256>>>();

    // ---- join: out = S @ G + d ----
    cudaStreamWaitEvent(0, evPool, 0);
    k_bgemm<<<dim3(16, 8), 128>>>(pSh, pSl, pGh, pGl,
                                  out, nullptr, nullptr, pD);
}

// round 14
// speedup vs baseline: 1.4815x; 1.4815x over previous
#include <cuda_runtime.h>
#include <cuda_bf16.h>
#include <mma.h>

using namespace nvcuda;
typedef __nv_bfloat16 bf;

// Problem constants (fixed by setup_inputs)
#define H 512
#define T_TREES 1024

#define GRID   296          // 2 blocks/SM on 148+ SMs, guaranteed co-resident
#define COMPB  256          // compute blocks (gemm grid 64 tiles x splitK 4)
#define POOLB  (GRID - COMPB)
#define POOL_ITEMS   131072            // 1024 trees x 128 float4 cols
#define POOL_SPLIT   98304             // items done by pool blocks; rest by comp blocks

// ---------------- device scratch (no allocs allowed) ----------------
__device__ bf g_WsT_h[H * H], g_WsT_l[H * H];
__device__ bf g_WzfT_h[H * H], g_WzfT_l[H * H];
__device__ bf g_N_h[H * H],  g_N_l[H * H];
__device__ bf g_N2_h[H * H], g_N2_l[H * H];
__device__ bf g_G_h[H * H],  g_G_l[H * H];
__device__ bf g_S_h[T_TREES * H], g_S_l[T_TREES * H];
__device__ float g_Nf[H * H];
__device__ float g_N2f[H * H];
__device__ float g_c[H];
__device__ float g_d[H];
__device__ float g_part1[4 * H * H];        // N partials
__device__ float g_part2[4 * H * H];        // N2 partials
__device__ float g_part3[4 * H * H];        // G partials
__device__ float g_partF[2 * T_TREES * H];  // final partials
__device__ unsigned long long g_bar[8];     // monotonic barrier counters

__device__ __forceinline__ void split2(float a, bf* h, bf* l) {
    bf hh = __float2bfloat16(a);
    *h = hh;
    *l = __float2bfloat16(a - __bfloat162float(hh));
}

// Monotonic-epoch grid barrier: counters never reset, so graph replays are safe.
__device__ __forceinline__ void gbar(int id, unsigned expected) {
    __syncthreads();
    if (threadIdx.x == 0) {
        __threadfence();
        unsigned long long my = atomicAdd(&g_bar[id], 1ULL) + 1ULL;
        unsigned long long target =
            ((my + (unsigned long long)expected - 1ULL) / expected) * expected;
        while (*((volatile unsigned long long*)&g_bar[id]) < target)
            __nanosleep(64);
    }
    __syncthreads();
}

// ---------------- one pooled column-sum item ----------------
__device__ __forceinline__ void pool_one(const float4* __restrict__ x4, int idx) {
    int t = idx >> 7, q = idx & 127;
    const float4* p = x4 + (size_t)t * 8192 + q;
    float4 s = make_float4(0.f, 0.f, 0.f, 0.f);
#pragma unroll 16
    for (int r = 0; r < 64; ++r) {
        float4 v = p[(size_t)r * 128];
        s.x += v.x; s.y += v.y; s.z += v.z; s.w += v.w;
    }
    int o = t * H + q * 4;
    split2(s.x, &g_S_h[o + 0], &g_S_l[o + 0]);
    split2(s.y, &g_S_h[o + 1], &g_S_l[o + 1]);
    split2(s.z, &g_S_h[o + 2], &g_S_l[o + 2]);
    split2(s.w, &g_S_h[o + 3], &g_S_l[o + 3]);
}

// ---------------- bf16x2-split wmma GEMM tile (proven math from R13) ----------------
// 256 threads, 8 warps (2x4), 64x64 tile, BK=32 double-buffered, 3-pass hi/lo.
// Writes fp32 tile to Cdst (row stride 512).
__device__ __forceinline__ void tile_gemm(
    const bf* __restrict__ Ah, const bf* __restrict__ Al,
    const bf* __restrict__ Bh, const bf* __restrict__ Bl,
    float* __restrict__ Cdst,
    int rb, int cb, int k0, int nk, char* s_raw)
{
    bf (*sA)[64][40] = reinterpret_cast<bf (*)[64][40]>(s_raw);          // [buf*2+hl]
    bf (*sB)[32][72] = reinterpret_cast<bf (*)[32][72]>(s_raw + 20480);

    const int tid = threadIdx.x;
    const int wid = tid >> 5;
    const int wr = (wid >> 2) * 32, wc = (wid & 3) * 16;

    const int ra = tid >> 2, ka = (tid & 3) * 8;     // A loader
    const int kb = tid >> 3, cq = (tid & 7) * 8;     // B loader

    const bf* pAh = Ah + (size_t)(rb + ra) * H + k0 + ka;
    const bf* pAl = Al + (size_t)(rb + ra) * H + k0 + ka;
    const bf* pBh = Bh + (size_t)(k0 + kb) * H + cb + cq;
    const bf* pBl = Bl + (size_t)(k0 + kb) * H + cb + cq;

    uint4 rAh = *(const uint4*)pAh;
    uint4 rAl = *(const uint4*)pAl;
    uint4 rBh = *(const uint4*)pBh;
    uint4 rBl = *(const uint4*)pBl;
    *(uint4*)&sA[0][ra][ka] = rAh;
    *(uint4*)&sA[1][ra][ka] = rAl;
    *(uint4*)&sB[0][kb][cq] = rBh;
    *(uint4*)&sB[1][kb][cq] = rBl;
    __syncthreads();

    wmma::fragment<wmma::accumulator, 16, 16, 16, float> acc[2];
    wmma::fill_fragment(acc[0], 0.f);
    wmma::fill_fragment(acc[1], 0.f);

    for (int kt = 0; kt < nk; ++kt) {
        int cur = kt & 1, nxt = cur ^ 1;
        if (kt + 1 < nk) {
            int off = (kt + 1) * 32;
            rAh = *(const uint4*)(pAh + off);
            rAl = *(const uint4*)(pAl + off);
            rBh = *(const uint4*)(pBh + (size_t)off * H);
            rBl = *(const uint4*)(pBl + (size_t)off * H);
        }
#pragma unroll
        for (int kk = 0; kk < 32; kk += 16) {
            wmma::fragment<wmma::matrix_a, 16, 16, 16, bf, wmma::row_major> fa;
            wmma::fragment<wmma::matrix_b, 16, 16, 16, bf, wmma::row_major> fbh, fbl;
            wmma::load_matrix_sync(fbh, &sB[cur * 2 + 0][kk][wc], 72);
            wmma::load_matrix_sync(fbl, &sB[cur * 2 + 1][kk][wc], 72);
#pragma unroll
            for (int i = 0; i < 2; ++i) {
                wmma::load_matrix_sync(fa, &sA[cur * 2 + 0][wr + i * 16][kk], 40);
                wmma::mma_sync(acc[i], fa, fbh, acc[i]);
                wmma::mma_sync(acc[i], fa, fbl, acc[i]);
            }
#pragma unroll
            for (int i = 0; i < 2; ++i) {
                wmma::load_matrix_sync(fa, &sA[cur * 2 + 1][wr + i * 16][kk], 40);
                wmma::mma_sync(acc[i], fa, fbh, acc[i]);
            }
        }
        if (kt + 1 < nk) {
            *(uint4*)&sA[nxt * 2 + 0][ra][ka] = rAh;
            *(uint4*)&sA[nxt * 2 + 1][ra][ka] = rAl;
            *(uint4*)&sB[nxt * 2 + 0][kb][cq] = rBh;
            *(uint4*)&sB[nxt * 2 + 1][kb][cq] = rBl;
        }
        __syncthreads();
    }

    // epilogue: stage accumulators (alias smem), then coalesced fp32 write
    float (*sC)[68] = reinterpret_cast<float (*)[68]>(s_raw);
#pragma unroll
    for (int i = 0; i < 2; ++i)
        wmma::store_matrix_sync(&sC[wr + i * 16][wc], acc[i], 68, wmma::mem_row_major);
    __syncthreads();
#pragma unroll
    for (int rep = 0; rep < 4; ++rep) {
        int e = rep * 256 + tid;
        int row = e >> 4, c4 = (e & 15) * 4;
        *(float4*)&Cdst[(size_t)(rb + row) * H + cb + c4] = *(float4*)&sC[row][c4];
    }
    __syncthreads();   // smem reusable by caller
}

// ---------------- combine 4 split-K partials, write fp32 (opt) + hi/lo ----------------
__device__ __forceinline__ void combine4(const float* __restrict__ part,
                                         float* __restrict__ dstF,
                                         bf* __restrict__ dstH, bf* __restrict__ dstL,
                                         int b)
{
    int i = b * 256 + threadIdx.x;   // 0..65535 float4 positions
    const float4* p = (const float4*)part;
    float4 r = p[i];
    float4 a = p[i + 65536], c = p[i + 131072], e = p[i + 196608];
    r.x += a.x + c.x + e.x;
    r.y += a.y + c.y + e.y;
    r.z += a.z + c.z + e.z;
    r.w += a.w + c.w + e.w;
    if (dstF) ((float4*)dstF)[i] = r;
    int o = i * 4;
    split2(r.x, dstH + o + 0, dstL + o + 0);
    split2(r.y, dstH + o + 1, dstL + o + 1);
    split2(r.z, dstH + o + 2, dstL + o + 2);
    split2(r.w, dstH + o + 3, dstL + o + 3);
}

// ---------------- the mega kernel ----------------
__global__ __launch_bounds__(256, 2)
void k_mega(const float4* __restrict__ x4, const float* __restrict__ Wz,
            const float* __restrict__ bzv, const float* __restrict__ Wzf,
            const float* __restrict__ bzf, float* __restrict__ out)
{
    __shared__ __align__(16) char s_raw[38912];
    const int b = blockIdx.x;
    const int tid = threadIdx.x;

    if (b < COMPB) {
        // ================= P0: prep (WsT, WzfT transposed+split; c) =================
        {
            float (*tile)[33] = reinterpret_cast<float (*)[33]>(s_raw);
            int tx = tid & 31, ty = tid >> 5;
            int bx = b & 15, by = b >> 4;
#pragma unroll
            for (int i = 0; i < 4; ++i) {
                int r = by * 32 + ty + i * 8;
                int c = bx * 32 + tx;
                tile[ty + i * 8][tx] =
                    Wz[0 * H * H + r * H + c] + Wz[1 * H * H + r * H + c] +
                    Wz[2 * H * H + r * H + c] + Wz[3 * H * H + r * H + c];
            }
            __syncthreads();
#pragma unroll
            for (int i = 0; i < 4; ++i) {
                int idx = (bx * 32 + ty + i * 8) * H + by * 32 + tx;
                split2(tile[tx][ty + i * 8], &g_WsT_h[idx], &g_WsT_l[idx]);
            }
            __syncthreads();
#pragma unroll
            for (int i = 0; i < 4; ++i)
                tile[ty + i * 8][tx] = Wzf[(by * 32 + ty + i * 8) * H + bx * 32 + tx];
            __syncthreads();
#pragma unroll
            for (int i = 0; i < 4; ++i) {
                int idx = (bx * 32 + ty + i * 8) * H + by * 32 + tx;
                split2(tile[tx][ty + i * 8], &g_WzfT_h[idx], &g_WzfT_l[idx]);
            }
            __syncthreads();
            if (b < 2) {   // c = 4 * (Wzf @ bsum + bzf)
                float* sb_ = reinterpret_cast<float*>(s_raw);
#pragma unroll
                for (int i = 0; i < 2; ++i) {
                    int hh = tid + i * 256;
                    sb_[hh] = bzv[hh] + bzv[H + hh] + bzv[2 * H + hh] + bzv[3 * H + hh];
                }
                __syncthreads();
                int j = b * 256 + tid;
                float acc = 0.f;
#pragma unroll 8
                for (int h = 0; h < H; ++h)
                    acc += Wzf[(size_t)j * H + h] * sb_[h];
                g_c[j] = 4.0f * (acc + bzf[j]);
            }
        }
        gbar(0, COMPB);

        const int gx = (b & 7) * 64, gy = ((b >> 3) & 7) * 64, gz = b >> 6; // splitK4

        // ================= N = WsT @ WzfT =================
        tile_gemm(g_WsT_h, g_WsT_l, g_WzfT_h, g_WzfT_l,
                  g_part1 + (size_t)gz * H * H, gx, gy, gz * 128, 4, s_raw);
        gbar(1, COMPB);
        combine4(g_part1, g_Nf, g_N_h, g_N_l, b);
        gbar(2, COMPB);

        // ================= N2 = N @ N =================
        tile_gemm(g_N_h, g_N_l, g_N_h, g_N_l,
                  g_part2 + (size_t)gz * H * H, gx, gy, gz * 128, 4, s_raw);
        gbar(3, COMPB);
        combine4(g_part2, g_N2f, g_N2_h, g_N2_l, b);
        gbar(4, COMPB);

        // ================= G = N2 @ N =================
        tile_gemm(g_N2_h, g_N2_l, g_N_h, g_N_l,
                  g_part3 + (size_t)gz * H * H, gx, gy, gz * 128, 4, s_raw);
        gbar(5, COMPB);
        combine4(g_part3, nullptr, g_G_h, g_G_l, b);

        // d = 16 M^2 c + 4 M c + c   (blocks 0,1)
        if (b < 2) {
            int j = b * 256 + tid;
            float acc = 0.f;
#pragma unroll 8
            for (int h = 0; h < H; ++h) {
                float ch = g_c[h];
                acc += ch * (16.0f * g_N2f[h * H + j] + 4.0f * g_Nf[h * H + j]);
            }
            g_d[j] = acc + g_c[j];
        }

        // help finish the pool (items POOL_SPLIT..end)
        {
            int gid = b * 256 + tid;
            if (gid < POOL_ITEMS - POOL_SPLIT)
                pool_one(x4, POOL_SPLIT + gid);
        }
    } else {
        // ================= pool blocks: stream x concurrently =================
        for (int idx = (b - COMPB) * 256 + tid; idx < POOL_SPLIT; idx += POOLB * 256)
            pool_one(x4, idx);
    }

    gbar(6, GRID);   // full join: S, G, d all ready

    // ================= final: out_partials = S @ G  (splitK 2) =================
    if (b < COMPB) {
        int t = b & 127;
        int rb = (t & 15) * 64, cb = ((t >> 4) & 7) * 64, z = b >> 7;
        tile_gemm(g_S_h, g_S_l, g_G_h, g_G_l,
                  g_partF + (size_t)z * T_TREES * H, rb, cb, z * 256, 8, s_raw);
    }
    gbar(7, GRID);

    // ================= combineF: out = partF0 + partF1 + d =================
    for (int i = b * 256 + tid; i < T_TREES * H / 4; i += GRID * 256) {
        const float4* p = (const float4*)g_partF;
        float4 r = p[i], v = p[i + 131072];
        float4 dv = ((const float4*)g_d)[i & 127];
        r.x += v.x + dv.x;
        r.y += v.y + dv.y;
        r.z += v.z + dv.z;
        r.w += v.w + dv.w;
        ((float4*)out)[i] = r;
    }
}

// ---------------- launch: ONE kernel, no streams, no events ----------------
extern "C" void kernel_launch(void* const* d_in, const int* in_sizes, int n_in,
                              void* d_out, int out_size) {
    const float* x   = (const float*)d_in[0];
    const float* Wz  = (const float*)d_in[1];
    const float* bz  = (const float*)d_in[2];
    const float* Wzf = (const float*)d_in[3];
    const float* bzf = (const float*)d_in[4];
    float* out = (float*)d_out;

    k_mega<<<GRID, 256>>>((const float4*)x, Wz, bz, Wzf, bzf, out);
}